// round 12
// baseline (speedup 1.0000x reference)
#include <cuda_runtime.h>
#include <cuda_fp16.h>

// ---------------------------------------------------------------------------
// N=512, MAX_DIST=16, H=32, N_SPATIAL=64, BOND_TYPES=32.
// edge_sum[i,j,k] = sum_d T[d][edge_input[i,j,d]][k],  T[d] = edge_table @ W[d]
// R12: prep = T-precompute + index pack + ALL of phi_spd (float4 LDS gather,
// STG.64 stores, 528 blocks x 256 thr for latency hiding). Main kernel =
// validated R11 loop (conflict-free LDS.32 T-gather, fp16 group trees, work
// stealing), now computing 1/sp inline from spatial_pos (g_rden removed).
// ---------------------------------------------------------------------------

#define NN        512
#define PAIRS     (NN * NN)          // 262144
#define MAXD      16
#define H         32
#define NSPAT     64
#define T2_ELEMS  (MAXD * 16 * 32)   // 8192 half2 = 32KB
#define SMEM_BYTES (T2_ELEMS * 4)    // 32768 (main kernel: shT only)
#define GRID      888               // 6 blocks/SM * 148 SMs
#define N_TASKS   4096              // 1024 tiles(256 pairs) * 4 k-quarters

__device__ __half2   g_T2[T2_ELEMS];   // [d][k2][e]
__device__ uint4     g_packed[PAIRS];  // 16 indices, pre-scaled x4, one byte each
__device__ unsigned  g_task_counter;

// Blocks 0..15: T[d]. Blocks 16..527: pack + phi_spd (2 adjacent pairs/thread).
__global__ __launch_bounds__(256)
void prep_kernel(const float* __restrict__ edge_table,
                 const float* __restrict__ W,
                 const int* __restrict__ edge_input,
                 const int* __restrict__ spatial_pos,
                 const float* __restrict__ spd_table,
                 float* __restrict__ out) {
    __shared__ float4 shBuf[512];   // 8KB: T: shE+shW ; pack: spd as [k4][sp]
    int t = threadIdx.x;

    if (blockIdx.x < MAXD) {
        float* shE = (float*)shBuf;            // [h][e]
        float* shW = (float*)shBuf + H * H;    // [h][k]
        int d = blockIdx.x;
        for (int i = t; i < H * H; i += 256) {
            int e = i >> 5, h = i & 31;
            shE[h * H + e] = edge_table[i];
            shW[i] = W[d * (H * H) + i];
        }
        __syncthreads();
        int e = t & 31;
#pragma unroll
        for (int rep = 0; rep < 2; ++rep) {
            int k2 = (t >> 5) + 8 * rep;
            float s0 = 0.0f, s1 = 0.0f;
#pragma unroll
            for (int h = 0; h < H; ++h) {
                float ev = shE[h * H + e];          // bank = e, conflict-free
                s0 += ev * shW[h * H + 2 * k2];     // broadcast
                s1 += ev * shW[h * H + 2 * k2 + 1];
            }
            g_T2[d * 512 + k2 * 32 + e] = __floats2half2_rn(s0, s1);
        }
        return;
    }

    if (blockIdx.x == MAXD && t == 0) g_task_counter = 0u;

    // Stage spd as float4: shBuf[k4*64 + sp] = spd_table[sp][4k4..4k4+3]
    {
        int k4 = t >> 6;          // 0..3 (first 256), loop covers 512 entries
#pragma unroll
        for (int rep = 0; rep < 2; ++rep) {
            int idx = t + rep * 256;
            int kk4 = idx >> 6;
            int sp  = idx & 63;
            shBuf[kk4 * 64 + sp] = ((const float4*)spd_table)[sp * 8 + kk4];
        }
        (void)k4;
    }
    __syncthreads();

    int pA = ((blockIdx.x - MAXD) * 256 + t) * 2;   // 512 blocks cover PAIRS

    // Pack indices for both pairs (byte offsets, x4)
#pragma unroll
    for (int pp = 0; pp < 2; ++pp) {
        int pair = pA + pp;
        const int4* ep = (const int4*)edge_input + pair * 4;
        int4 a = ep[0], b = ep[1], c = ep[2], e4 = ep[3];
        uint4 r;
        r.x = ((unsigned)a.x  << 2) | ((unsigned)a.y  << 10) | ((unsigned)a.z  << 18) | ((unsigned)a.w  << 26);
        r.y = ((unsigned)b.x  << 2) | ((unsigned)b.y  << 10) | ((unsigned)b.z  << 18) | ((unsigned)b.w  << 26);
        r.z = ((unsigned)c.x  << 2) | ((unsigned)c.y  << 10) | ((unsigned)c.z  << 18) | ((unsigned)c.w  << 26);
        r.w = ((unsigned)e4.x << 2) | ((unsigned)e4.y << 10) | ((unsigned)e4.z << 18) | ((unsigned)e4.w << 26);
        g_packed[pair] = r;
    }

    // phi_spd for both pairs: 8 x (2 LDS.128 + 4 STG.64)
    int2 s = ((const int2*)spatial_pos)[pA >> 1];
#pragma unroll
    for (int k4 = 0; k4 < 8; ++k4) {
        float4 va = shBuf[k4 * 64 + s.x];
        float4 vb = shBuf[k4 * 64 + s.y];
        float* o = out + (4 * k4) * PAIRS + pA;
        *(float2*)(o + 0 * PAIRS) = make_float2(va.x, vb.x);
        *(float2*)(o + 1 * PAIRS) = make_float2(va.y, vb.y);
        *(float2*)(o + 2 * PAIRS) = make_float2(va.z, vb.z);
        *(float2*)(o + 3 * PAIRS) = make_float2(va.w, vb.w);
    }
}

__global__ __launch_bounds__(256, 6)
void bond_encoding_kernel(const int* __restrict__ spatial_pos,
                          float* __restrict__ out) {
    extern __shared__ float sh[];
    __half2* shT = (__half2*)sh;              // [d][k2][e], 32KB
    __shared__ int mail[2];
    const int t = threadIdx.x;

    {
        const float4* src = (const float4*)g_T2;
        float4* dst = (float4*)sh;
#pragma unroll
        for (int i = t; i < T2_ELEMS / 4; i += 256)
            dst[i] = src[i];
    }
    if (t == 0) mail[0] = (int)atomicAdd(&g_task_counter, 1u);
    __syncthreads();

    int task = mail[0];
    int slot = 1;
    while (task < N_TASKS) {
        if (t == 0) mail[slot] = (int)atomicAdd(&g_task_counter, 1u);

        int tile = task >> 2;
        int kq   = task & 3;                  // k-quarter: 8 heads
        int pair = tile * 256 + t;

        uint4 pk4 = g_packed[pair];           // one LDG.128: all 16 indices *4
        unsigned pk[4] = { pk4.x, pk4.y, pk4.z, pk4.w };
        int sp = __ldg(spatial_pos + pair);
        float rden = 1.0f / fmaxf((float)sp, 1.0f);

        float acc[8];
#pragma unroll
        for (int j = 0; j < 8; ++j) acc[j] = 0.0f;

#pragma unroll
        for (int g = 0; g < 4; ++g) {         // d-group of 4: d = 4g..4g+3
            const char* base = (const char*)(shT + ((4 * g) * 16 + kq * 4) * 32);
            unsigned o0 =  pk[g]        & 0xFCu;
            unsigned o1 = (pk[g] >> 8)  & 0xFCu;
            unsigned o2 = (pk[g] >> 16) & 0xFCu;
            unsigned o3 = (pk[g] >> 24);
            const __half2* p0 = (const __half2*)(base          + o0);
            const __half2* p1 = (const __half2*)(base + 2048   + o1);
            const __half2* p2 = (const __half2*)(base + 4096   + o2);
            const __half2* p3 = (const __half2*)(base + 6144   + o3);
#pragma unroll
            for (int j = 0; j < 4; ++j) {     // 4 k2 slots in this quarter
                __half2 tt = __hadd2(__hadd2(p0[j * 32], p1[j * 32]),
                                     __hadd2(p2[j * 32], p3[j * 32]));
                float2 f = __half22float2(tt);
                acc[2 * j]     = fmaf(f.x, rden, acc[2 * j]);
                acc[2 * j + 1] = fmaf(f.y, rden, acc[2 * j + 1]);
            }
        }

        float* oe = out + (H + kq * 8) * PAIRS + pair;
#pragma unroll
        for (int j = 0; j < 8; ++j)
            oe[j * PAIRS] = acc[j];

        __syncthreads();       // publishes mail[slot]
        task = mail[slot];
        slot ^= 1;
    }
}

extern "C" void kernel_launch(void* const* d_in, const int* in_sizes, int n_in,
                              void* d_out, int out_size) {
    const int*   spatial_pos = nullptr;
    const int*   edge_input  = nullptr;
    const float* spd_table   = nullptr;
    const float* edge_table  = nullptr;
    const float* W           = nullptr;
    for (int i = 0; i < n_in; ++i) {
        switch (in_sizes[i]) {
            case PAIRS:          spatial_pos = (const int*)d_in[i];   break;
            case PAIRS * MAXD:   edge_input  = (const int*)d_in[i];   break;
            case NSPAT * H:      spd_table   = (const float*)d_in[i]; break;
            case H * H:          edge_table  = (const float*)d_in[i]; break;
            case NSPAT * H * H:  W           = (const float*)d_in[i]; break;
            default: break;
        }
    }

    // 16 T-blocks + 512 pack blocks (256 thr, 2 pairs/thread)
    prep_kernel<<<MAXD + PAIRS / 512, 256>>>(edge_table, W, edge_input,
                                             spatial_pos, spd_table,
                                             (float*)d_out);

    cudaFuncSetAttribute(bond_encoding_kernel,
                         cudaFuncAttributeMaxDynamicSharedMemorySize, SMEM_BYTES);
    bond_encoding_kernel<<<GRID, 256, SMEM_BYTES>>>(spatial_pos, (float*)d_out);
}